// round 2
// baseline (speedup 1.0000x reference)
#include <cuda_runtime.h>
#include <math.h>

#define DM 512
#define NH 8
#define ED 64
#define NB 2
#define SL 2048
#define MT (NB*SL)          // 4096 rows
#define NBH (NB*NH)         // 16 sequences
#define CK 128              // chunk length
#define NCH (SL/CK)         // 16 chunks

// ---------------- scratch (static device globals; no runtime alloc) --------
__device__ float g_q[MT*DM];
__device__ float g_k[MT*DM];
__device__ float g_v[MT*DM];
__device__ float g_attn[MT*DM];
__device__ float g_y[MT*DM];
__device__ float g_Sloc[NBH*NCH*ED*ED];
__device__ float g_Sin [NBH*NCH*ED*ED];
__device__ float g_zloc[NBH*NCH*ED];
__device__ float g_zin [NBH*NCH*ED];

__device__ __forceinline__ float lam_of(const float* dl, int h){
    return 0.99f + 0.01f/(1.0f + expf(-dl[h]));
}

// ---------------- generic 128x128 fp32 GEMM, BK=8, 256 thr, 8x8/thr -------
// MODE 0: qkv = x @ W_qkv + b, epilogue splits into q/k/v with ELU feature maps
// MODE 1: y   = attn @ W_out + b
template<int MODE>
__global__ __launch_bounds__(256) void sgemm_kernel(const float* __restrict__ A,
                                                    const float* __restrict__ W,
                                                    const float* __restrict__ bias)
{
    constexpr int N = (MODE==0) ? 3*DM : DM;
    constexpr int K = DM;
    __shared__ float As[8][128];
    __shared__ float Bs[8][128];
    const float* Ap = (MODE==0) ? A : g_attn;
    const int t  = threadIdx.x;
    const int m0 = blockIdx.y*128, n0 = blockIdx.x*128;
    const int tx = t & 15, ty = t >> 4;
    const int arow = t >> 1, acol = (t & 1)*4;
    const int brow = t >> 5, bcol = (t & 31)*4;

    float acc[8][8];
    #pragma unroll
    for (int i=0;i<8;i++)
        #pragma unroll
        for (int j=0;j<8;j++) acc[i][j]=0.f;

    for (int k0 = 0; k0 < K; k0 += 8) {
        float4 av = *(const float4*)(Ap + (size_t)(m0+arow)*K + k0 + acol);
        As[acol+0][arow]=av.x; As[acol+1][arow]=av.y;
        As[acol+2][arow]=av.z; As[acol+3][arow]=av.w;
        *(float4*)(&Bs[brow][bcol]) = *(const float4*)(W + (size_t)(k0+brow)*N + n0 + bcol);
        __syncthreads();
        #pragma unroll
        for (int k=0;k<8;k++){
            float4 a0 = *(const float4*)&As[k][ty*4];
            float4 a1 = *(const float4*)&As[k][ty*4+64];
            float4 b0 = *(const float4*)&Bs[k][tx*4];
            float4 b1 = *(const float4*)&Bs[k][tx*4+64];
            float a[8] = {a0.x,a0.y,a0.z,a0.w,a1.x,a1.y,a1.z,a1.w};
            float b[8] = {b0.x,b0.y,b0.z,b0.w,b1.x,b1.y,b1.z,b1.w};
            #pragma unroll
            for (int i=0;i<8;i++)
                #pragma unroll
                for (int j=0;j<8;j++) acc[i][j] = fmaf(a[i], b[j], acc[i][j]);
        }
        __syncthreads();
    }
    #pragma unroll
    for (int i=0;i<8;i++){
        const int m = m0 + ty*4 + (i&3) + (i>>2)*64;
        #pragma unroll
        for (int j=0;j<8;j++){
            const int n = n0 + tx*4 + (j&3) + (j>>2)*64;
            float v = acc[i][j] + bias[n];
            if (MODE==0){
                if (n < DM){                 // q: (elu+1)/sqrt(E)
                    float e = (v>0.f) ? v+1.f : expf(v);
                    g_q[(size_t)m*DM + n] = e*0.125f;
                } else if (n < 2*DM){        // k: elu+1
                    float e = (v>0.f) ? v+1.f : expf(v);
                    g_k[(size_t)m*DM + (n-DM)] = e;
                } else {                     // v
                    g_v[(size_t)m*DM + (n-2*DM)] = v;
                }
            } else {
                g_y[(size_t)m*DM + n] = v;
            }
        }
    }
}

// ---------------- per-chunk local state: S_loc = sum_j lam^{C-1-j} k_j v_j^T
__global__ __launch_bounds__(256) void chunk_local_kernel(const float* __restrict__ dl)
{
    extern __shared__ float sh[];
    float* Kc = sh;              // 128*64
    float* Vc = Kc + CK*ED;      // 128*64
    float* pw = Vc + CK*ED;      // 128
    const int c = blockIdx.x, bh = blockIdx.y;
    const int b = bh / NH, h = bh % NH;
    const int t = threadIdx.x;
    const float lam = lam_of(dl, h);
    if (t < CK) pw[t] = exp2f((float)t * log2f(lam));

    const size_t rowbase = ((size_t)b*SL + (size_t)c*CK)*DM + h*ED;
    for (int vi = t; vi < CK*ED/4; vi += 256){
        const int j = vi >> 4, e4 = (vi & 15)*4;
        *(float4*)&Kc[j*ED + e4] = *(const float4*)&g_k[rowbase + (size_t)j*DM + e4];
        *(float4*)&Vc[j*ED + e4] = *(const float4*)&g_v[rowbase + (size_t)j*DM + e4];
    }
    __syncthreads();

    const int e = t >> 2, f0 = (t & 3)*16;
    float acc[16];
    #pragma unroll
    for (int i=0;i<16;i++) acc[i]=0.f;
    float zacc = 0.f;
    for (int j = 0; j < CK; j++){
        const float kw = pw[CK-1-j] * Kc[j*ED + e];
        zacc += kw;
        #pragma unroll
        for (int i=0;i<16;i++) acc[i] = fmaf(kw, Vc[j*ED + f0 + i], acc[i]);
    }
    const size_t sb = ((size_t)bh*NCH + c)*ED*ED;
    #pragma unroll
    for (int i=0;i<16;i++) g_Sloc[sb + e*ED + f0 + i] = acc[i];
    if ((t & 3) == 0) g_zloc[((size_t)bh*NCH + c)*ED + e] = zacc;
}

// ---------------- inter-chunk prefix scan of states (16 sequential steps) --
__global__ __launch_bounds__(256) void scan_kernel(const float* __restrict__ dl)
{
    const int bh = blockIdx.x;
    const int h = bh % NH;
    const int t = threadIdx.x;
    const float lam  = lam_of(dl, h);
    const float lamC = exp2f((float)CK * log2f(lam));
    float s[16];
    #pragma unroll
    for (int i=0;i<16;i++) s[i]=0.f;
    float z = 0.f;
    for (int c = 0; c < NCH; c++){
        const size_t base = ((size_t)bh*NCH + c)*ED*ED + (size_t)t*16;
        #pragma unroll
        for (int i=0;i<16;i+=4)
            *(float4*)&g_Sin[base+i] = make_float4(s[i],s[i+1],s[i+2],s[i+3]);
        if (t < ED) g_zin[((size_t)bh*NCH+c)*ED + t] = z;
        #pragma unroll
        for (int i=0;i<16;i+=4){
            float4 lv = *(const float4*)&g_Sloc[base+i];
            s[i]   = lamC*s[i]   + lv.x;
            s[i+1] = lamC*s[i+1] + lv.y;
            s[i+2] = lamC*s[i+2] + lv.z;
            s[i+3] = lamC*s[i+3] + lv.w;
        }
        if (t < ED) z = lamC*z + g_zloc[((size_t)bh*NCH+c)*ED + t];
    }
}

// ---------------- per-chunk output --------------------------------------
// out_i = [ lam^{i+1} (Q S_in)_i + sum_{j<=i} lam^{i-j}(q_i.k_j) v_j ]
//       / [ lam^{i+1} (q_i.z_in) + sum_{j<=i} lam^{i-j}(q_i.k_j) + 1e-6 ]
__global__ __launch_bounds__(256) void chunk_out_kernel(const float* __restrict__ dl)
{
    extern __shared__ float sh[];
    float* Qs  = sh;              // 128 x 65
    float* Kt  = Qs  + 128*65;    // 64  x 132 (transposed K)
    float* Vs  = Kt  + 64*132;    // 128 x 68
    float* Ss  = Vs  + 128*68;    // 64  x 68
    float* Ps  = Ss  + 64*68;     // 128 x 132 (weighted scores)
    float* zs  = Ps  + 128*132;   // 64
    float* pw  = zs  + 64;        // 132 (lam^0..lam^128)
    float* dqs = pw  + 132;       // 128
    float* dens= dqs + 128;       // 128

    const int c = blockIdx.x, bh = blockIdx.y;
    const int b = bh / NH, h = bh % NH;
    const int t = threadIdx.x;
    const int tx = t & 15, ty = t >> 4;
    const float lam = lam_of(dl, h);
    if (t <= CK) pw[t] = exp2f((float)t * log2f(lam));

    const size_t rowbase = ((size_t)b*SL + (size_t)c*CK)*DM + h*ED;
    for (int vi = t; vi < CK*ED/4; vi += 256){
        const int r = vi >> 4, k4 = (vi & 15)*4;
        float4 qv = *(const float4*)&g_q[rowbase + (size_t)r*DM + k4];
        Qs[r*65 + k4+0]=qv.x; Qs[r*65 + k4+1]=qv.y;
        Qs[r*65 + k4+2]=qv.z; Qs[r*65 + k4+3]=qv.w;
        float4 kv = *(const float4*)&g_k[rowbase + (size_t)r*DM + k4];
        Kt[(k4+0)*132 + r]=kv.x; Kt[(k4+1)*132 + r]=kv.y;
        Kt[(k4+2)*132 + r]=kv.z; Kt[(k4+3)*132 + r]=kv.w;
        *(float4*)&Vs[r*68 + k4] = *(const float4*)&g_v[rowbase + (size_t)r*DM + k4];
    }
    const size_t sbase = ((size_t)bh*NCH + c)*ED*ED;
    for (int vi = t; vi < ED*ED/4; vi += 256){
        const int r = vi >> 4, f4 = (vi & 15)*4;
        *(float4*)&Ss[r*68 + f4] = *(const float4*)&g_Sin[sbase + r*ED + f4];
    }
    if (t < ED) zs[t] = g_zin[((size_t)bh*NCH+c)*ED + t];
    __syncthreads();

    // Phase 1: P = (Q K^T) with causal lam^{i-j} weighting
    {
        float accP[8][8];
        #pragma unroll
        for (int i=0;i<8;i++)
            #pragma unroll
            for (int j=0;j<8;j++) accP[i][j]=0.f;
        for (int k=0;k<ED;k++){
            float a[8];
            #pragma unroll
            for (int i=0;i<8;i++)
                a[i] = Qs[(ty*4 + (i&3) + (i>>2)*64)*65 + k];
            float4 b0 = *(const float4*)&Kt[k*132 + tx*4];
            float4 b1 = *(const float4*)&Kt[k*132 + tx*4 + 64];
            float bb[8] = {b0.x,b0.y,b0.z,b0.w,b1.x,b1.y,b1.z,b1.w};
            #pragma unroll
            for (int i=0;i<8;i++)
                #pragma unroll
                for (int j=0;j<8;j++) accP[i][j] = fmaf(a[i], bb[j], accP[i][j]);
        }
        #pragma unroll
        for (int i=0;i<8;i++){
            const int ii = ty*4 + (i&3) + (i>>2)*64;
            #pragma unroll
            for (int j=0;j<8;j++){
                const int jj = tx*4 + (j&3) + (j>>2)*64;
                const float w = (jj <= ii) ? pw[ii-jj] : 0.f;
                Ps[ii*132 + jj] = w * accP[i][j];
            }
        }
    }
    __syncthreads();

    // Phase 2: row sums (denominator pieces), threads 0..127
    if (t < CK){
        float d = 0.f;
        for (int j=0;j<CK;j++) d += Ps[t*132 + j];
        dens[t] = d;
        float q = 0.f;
        for (int k=0;k<ED;k++) q += Qs[t*65 + k] * zs[k];
        dqs[t] = q;
    }

    // Phase 3: acc1 = Q @ S_in ; acc2 = P @ V
    float acc1[8][4], acc2[8][4];
    #pragma unroll
    for (int i=0;i<8;i++)
        #pragma unroll
        for (int j=0;j<4;j++){ acc1[i][j]=0.f; acc2[i][j]=0.f; }
    for (int k=0;k<ED;k++){
        float4 sv = *(const float4*)&Ss[k*68 + tx*4];
        #pragma unroll
        for (int i=0;i<8;i++){
            const float qv = Qs[(ty*4 + (i&3) + (i>>2)*64)*65 + k];
            acc1[i][0] = fmaf(qv, sv.x, acc1[i][0]);
            acc1[i][1] = fmaf(qv, sv.y, acc1[i][1]);
            acc1[i][2] = fmaf(qv, sv.z, acc1[i][2]);
            acc1[i][3] = fmaf(qv, sv.w, acc1[i][3]);
        }
    }
    for (int k2=0;k2<CK;k2++){
        float4 vv = *(const float4*)&Vs[k2*68 + tx*4];
        #pragma unroll
        for (int i=0;i<8;i++){
            const float p = Ps[(ty*4 + (i&3) + (i>>2)*64)*132 + k2];
            acc2[i][0] = fmaf(p, vv.x, acc2[i][0]);
            acc2[i][1] = fmaf(p, vv.y, acc2[i][1]);
            acc2[i][2] = fmaf(p, vv.z, acc2[i][2]);
            acc2[i][3] = fmaf(p, vv.w, acc2[i][3]);
        }
    }
    __syncthreads();  // dens/dqs visible to everyone

    #pragma unroll
    for (int i=0;i<8;i++){
        const int ii = ty*4 + (i&3) + (i>>2)*64;
        const float pwi = pw[ii+1];
        const float dd  = pwi*dqs[ii] + dens[ii] + 1e-6f;
        const float inv = 1.f/dd;
        const int m = b*SL + c*CK + ii;
        #pragma unroll
        for (int j=0;j<4;j++){
            const float num = pwi*acc1[i][j] + acc2[i][j];
            g_attn[(size_t)m*DM + h*ED + tx*4 + j] = num*inv;
        }
    }
}

// ---------------- LayerNorm ------------------------------------------------
__global__ __launch_bounds__(128) void ln_kernel(const float* __restrict__ gg,
                                                 const float* __restrict__ bb,
                                                 float* __restrict__ out)
{
    const int row = blockIdx.x, t = threadIdx.x;
    __shared__ float red[8];
    float4 v = *(const float4*)&g_y[(size_t)row*DM + t*4];
    float s  = v.x+v.y+v.z+v.w;
    float s2 = v.x*v.x+v.y*v.y+v.z*v.z+v.w*v.w;
    #pragma unroll
    for (int o=16;o;o>>=1){
        s  += __shfl_xor_sync(0xffffffffu, s,  o);
        s2 += __shfl_xor_sync(0xffffffffu, s2, o);
    }
    const int w = t>>5;
    if ((t&31)==0){ red[w]=s; red[4+w]=s2; }
    __syncthreads();
    s  = red[0]+red[1]+red[2]+red[3];
    s2 = red[4]+red[5]+red[6]+red[7];
    const float mean = s*(1.0f/DM);
    const float var  = s2*(1.0f/DM) - mean*mean;
    const float inv  = rsqrtf(var + 1e-5f);
    float4 gv = *(const float4*)&gg[t*4];
    float4 bv = *(const float4*)&bb[t*4];
    float4 o;
    o.x = (v.x-mean)*inv*gv.x + bv.x;
    o.y = (v.y-mean)*inv*gv.y + bv.y;
    o.z = (v.z-mean)*inv*gv.z + bv.z;
    o.w = (v.w-mean)*inv*gv.w + bv.w;
    *(float4*)&out[(size_t)row*DM + t*4] = o;
}

// ---------------- launch ----------------------------------------------------
extern "C" void kernel_launch(void* const* d_in, const int* in_sizes, int n_in,
                              void* d_out, int out_size)
{
    const float* x     = (const float*)d_in[0];
    const float* W_qkv = (const float*)d_in[1];
    const float* b_qkv = (const float*)d_in[2];
    const float* W_out = (const float*)d_in[3];
    const float* b_out = (const float*)d_in[4];
    const float* dl    = (const float*)d_in[5];
    const float* ln_g  = (const float*)d_in[6];
    const float* ln_b  = (const float*)d_in[7];
    float* out = (float*)d_out;

    const int smem_cl = (CK*ED*2 + CK) * 4;                       // 66048 B
    const int smem_co = (128*65 + 64*132 + 128*68 + 64*68 +
                         128*132 + 64 + 132 + 128 + 128) * 4;     // 188688 B
    cudaFuncSetAttribute(chunk_local_kernel,
                         cudaFuncAttributeMaxDynamicSharedMemorySize, smem_cl);
    cudaFuncSetAttribute(chunk_out_kernel,
                         cudaFuncAttributeMaxDynamicSharedMemorySize, smem_co);

    sgemm_kernel<0><<<dim3(12,32),256>>>(x, W_qkv, b_qkv);
    chunk_local_kernel<<<dim3(NCH,NBH),256,smem_cl>>>(dl);
    scan_kernel<<<NBH,256>>>(dl);
    chunk_out_kernel<<<dim3(NCH,NBH),256,smem_co>>>(dl);
    sgemm_kernel<1><<<dim3(4,32),256>>>(nullptr, W_out, b_out);
    ln_kernel<<<MT,128>>>(ln_g, ln_b, out);
}

// round 5
// speedup vs baseline: 1.6267x; 1.6267x over previous
#include <cuda_runtime.h>
#include <math.h>
#include <stdint.h>

#define DM 512
#define NH 8
#define ED 64
#define NB 2
#define SL 2048
#define MT (NB*SL)          // 4096 rows
#define NBH (NB*NH)         // 16 sequences
#define CK 128              // chunk length
#define NCH (SL/CK)         // 16 chunks

// ---------------- scratch (static device globals; no runtime alloc) --------
__device__ float g_q[MT*DM];
__device__ float g_k[MT*DM];
__device__ float g_v[MT*DM];
__device__ float g_attn[MT*DM];
__device__ float g_y[MT*DM];
__device__ float g_WqkvT[3*DM*DM];   // [1536][512]
__device__ float g_WoutT[DM*DM];     // [512][512]
__device__ float g_Sloc[NBH*NCH*ED*ED];
__device__ float g_Sin [NBH*NCH*ED*ED];
__device__ float g_zloc[NBH*NCH*ED];
__device__ float g_zin [NBH*NCH*ED];

__device__ __forceinline__ float lam_of(const float* dl, int h){
    return 0.99f + 0.01f/(1.0f + expf(-dl[h]));
}
__device__ __forceinline__ uint32_t f2tf32(float x){
    uint32_t r; asm("cvt.rna.tf32.f32 %0, %1;" : "=r"(r) : "f"(x)); return r;
}
__device__ __forceinline__ void mma_tf32(float* c, const uint4& a, const uint2& b){
    asm volatile("mma.sync.aligned.m16n8k8.row.col.f32.tf32.tf32.f32 "
        "{%0,%1,%2,%3}, {%4,%5,%6,%7}, {%8,%9}, {%0,%1,%2,%3};"
        : "+f"(c[0]), "+f"(c[1]), "+f"(c[2]), "+f"(c[3])
        : "r"(a.x), "r"(a.y), "r"(a.z), "r"(a.w), "r"(b.x), "r"(b.y));
}

// ---------------- W transpose: Wt[n][k] = W[k][n] ---------------------------
__global__ void transpose_kernel(const float* __restrict__ W, float* __restrict__ Wt,
                                 int K, int N)
{
    __shared__ float tile[32][33];
    const int n0 = blockIdx.x*32, k0 = blockIdx.y*32;
    const int tx = threadIdx.x, ty = threadIdx.y;   // 32 x 8
    #pragma unroll
    for (int j=0;j<32;j+=8)
        tile[ty+j][tx] = W[(size_t)(k0+ty+j)*N + n0+tx];
    __syncthreads();
    #pragma unroll
    for (int j=0;j<32;j+=8)
        Wt[(size_t)(n0+ty+j)*K + k0+tx] = tile[tx][ty+j];
}

// =================== tf32 mma.sync GEMM: D = A @ Wt^T + b ===================
// Block 128x128, BK=32, 8 warps (wm 0..1, wn 0..3), warp tile 64x32,
// fragments m16n8k8. Fragment-packed smem, double-buffered.
// MODE 0: qkv = x @ W_qkv + b (epilogue: ELU maps, split q/k/v)
// MODE 1: y   = attn @ W_out + b
template<int MODE>
__global__ __launch_bounds__(256) void mma_gemm_kernel(const float* __restrict__ Ain,
                                                       const float* __restrict__ bias)
{
    extern __shared__ uint32_t sm[];        // 2 bufs x (A 4096 + B 4096) u32
    const float* A  = (MODE==0) ? Ain : g_attn;
    const float* Wt = (MODE==0) ? g_WqkvT : g_WoutT;
    const int m0 = blockIdx.y*128, n0 = blockIdx.x*128;
    const int t = threadIdx.x, lane = t&31, wid = t>>5;
    const int wm = wid&1, wn = wid>>1;

    // ---- loader constants ----
    const int c4    = (t&7)<<2;           // k-offset within 32-chunk (0,4..28)
    const int kkL   = c4>>3;              // which k-step (0..3)
    const int cregL = (c4>>2)&1;          // k<4 vs k>=4 within step
    const int rlo   = t>>3;               // row 0..31 (repeats +32*i)
    const int lane0 = (rlo&7)<<2;         // fragment lane base
    const int rhi   = (t>>6)&1;           // (row>>3)&1
    const int mt0   = t>>7;               // A mtile base (row>>4)
    const int nt0   = (t>>6)&3;           // B ntile base (row>>3)
    const int regA  = rhi + 2*cregL;

    float4 ra[4], rb[4];
    float acc[4][4][4];
    #pragma unroll
    for (int i=0;i<4;i++)
        #pragma unroll
        for (int j=0;j<4;j++)
            #pragma unroll
            for (int r=0;r<4;r++) acc[i][j][r]=0.f;

    auto ldg = [&](int c){
        const int k0 = c*32;
        #pragma unroll
        for (int i=0;i<4;i++){
            ra[i] = *(const float4*)&A [(size_t)(m0 + rlo + 32*i)*DM + k0 + c4];
            rb[i] = *(const float4*)&Wt[(size_t)(n0 + rlo + 32*i)*DM + k0 + c4];
        }
    };
    auto sts = [&](int buf){
        uint32_t* Ab = sm + buf*8192;
        uint32_t* Bb = Ab + 4096;
        #pragma unroll
        for (int i=0;i<4;i++){
            const int mt = mt0 + 2*i;                // 0..7
            const uint32_t ab = (uint32_t)(((mt*4 + kkL)*32 + lane0)*4 + regA);
            Ab[ab + 0*4] = f2tf32(ra[i].x);
            Ab[ab + 1*4] = f2tf32(ra[i].y);
            Ab[ab + 2*4] = f2tf32(ra[i].z);
            Ab[ab + 3*4] = f2tf32(ra[i].w);
            const int nt = nt0 + 4*i;                // 0..15
            const uint32_t bb = (uint32_t)(((nt*4 + kkL)*32 + lane0)*2 + cregL);
            Bb[bb + 0*2] = f2tf32(rb[i].x);
            Bb[bb + 1*2] = f2tf32(rb[i].y);
            Bb[bb + 2*2] = f2tf32(rb[i].z);
            Bb[bb + 3*2] = f2tf32(rb[i].w);
        }
    };
    auto compute = [&](int buf){
        const uint32_t* Ab = sm + buf*8192;
        const uint32_t* Bb = Ab + 4096;
        #pragma unroll
        for (int kk=0;kk<4;kk++){
            uint4 a[4]; uint2 b[4];
            #pragma unroll
            for (int i=0;i<4;i++)
                a[i] = *(const uint4*)&Ab[(((wm*4+i)*4+kk)*32 + lane)*4];
            #pragma unroll
            for (int j=0;j<4;j++)
                b[j] = *(const uint2*)&Bb[(((wn*4+j)*4+kk)*32 + lane)*2];
            #pragma unroll
            for (int i=0;i<4;i++)
                #pragma unroll
                for (int j=0;j<4;j++)
                    mma_tf32(acc[i][j], a[i], b[j]);
        }
    };

    ldg(0); sts(0); __syncthreads();
    #pragma unroll 1
    for (int c=0;c<16;c++){
        if (c<15) ldg(c+1);
        compute(c&1);
        if (c<15) sts((c+1)&1);
        __syncthreads();
    }

    // ---- epilogue: bias + activation + direct float2 stores ----
    int regi = 0; float* dst;
    if (MODE==0){
        regi = n0 >> 9;                          // 0:q 1:k 2:v
        dst = (regi==0) ? g_q : (regi==1) ? g_k : g_v;
    } else dst = g_y;
    const int nsub = (MODE==0) ? (n0 - regi*512) : n0;
    const int rowl = lane>>2, colp = (lane&3)*2;

    #pragma unroll
    for (int i=0;i<4;i++){
        #pragma unroll
        for (int j=0;j<4;j++){
            const int nn = n0   + wn*32 + j*8 + colp;   // bias index
            const int nc = nsub + wn*32 + j*8 + colp;   // dst col
            const float b0v = __ldg(&bias[nn]);
            const float b1v = __ldg(&bias[nn+1]);
            float v[4] = { acc[i][j][0] + b0v, acc[i][j][1] + b1v,
                           acc[i][j][2] + b0v, acc[i][j][3] + b1v };
            if (MODE==0 && regi==0){
                #pragma unroll
                for (int e=0;e<4;e++){ float x=(v[e]>0.f)?v[e]+1.f:expf(v[e]); v[e]=x*0.125f; }
            } else if (MODE==0 && regi==1){
                #pragma unroll
                for (int e=0;e<4;e++){ float x=(v[e]>0.f)?v[e]+1.f:expf(v[e]); v[e]=x; }
            }
            const int r0 = m0 + wm*64 + i*16 + rowl;
            *(float2*)&dst[(size_t)r0*DM + nc]     = make_float2(v[0], v[1]);
            *(float2*)&dst[(size_t)(r0+8)*DM + nc] = make_float2(v[2], v[3]);
        }
    }
}

// ---------------- per-chunk local state: S_loc = sum_j lam^{C-1-j} k_j v_j^T
__global__ __launch_bounds__(256) void chunk_local_kernel(const float* __restrict__ dl)
{
    extern __shared__ float sh[];
    float* Kc = sh;              // 128*64
    float* Vc = Kc + CK*ED;      // 128*64
    float* pw = Vc + CK*ED;      // 128
    const int c = blockIdx.x, bh = blockIdx.y;
    const int b = bh / NH, h = bh % NH;
    const int t = threadIdx.x;
    const float lam = lam_of(dl, h);
    if (t < CK) pw[t] = exp2f((float)t * log2f(lam));

    const size_t rowbase = ((size_t)b*SL + (size_t)c*CK)*DM + h*ED;
    for (int vi = t; vi < CK*ED/4; vi += 256){
        const int j = vi >> 4, e4 = (vi & 15)*4;
        *(float4*)&Kc[j*ED + e4] = *(const float4*)&g_k[rowbase + (size_t)j*DM + e4];
        *(float4*)&Vc[j*ED + e4] = *(const float4*)&g_v[rowbase + (size_t)j*DM + e4];
    }
    __syncthreads();

    const int e = t >> 2, f0 = (t & 3)*16;
    float acc[16];
    #pragma unroll
    for (int i=0;i<16;i++) acc[i]=0.f;
    float zacc = 0.f;
    for (int j = 0; j < CK; j++){
        const float kw = pw[CK-1-j] * Kc[j*ED + e];
        zacc += kw;
        #pragma unroll
        for (int i=0;i<16;i++) acc[i] = fmaf(kw, Vc[j*ED + f0 + i], acc[i]);
    }
    const size_t sb = ((size_t)bh*NCH + c)*ED*ED;
    #pragma unroll
    for (int i=0;i<16;i++) g_Sloc[sb + e*ED + f0 + i] = acc[i];
    if ((t & 3) == 0) g_zloc[((size_t)bh*NCH + c)*ED + e] = zacc;
}

// ---------------- inter-chunk prefix scan of states (16 sequential steps) --
__global__ __launch_bounds__(256) void scan_kernel(const float* __restrict__ dl)
{
    const int bh = blockIdx.x;
    const int h = bh % NH;
    const int t = threadIdx.x;
    const float lam  = lam_of(dl, h);
    const float lamC = exp2f((float)CK * log2f(lam));
    float s[16];
    #pragma unroll
    for (int i=0;i<16;i++) s[i]=0.f;
    float z = 0.f;
    for (int c = 0; c < NCH; c++){
        const size_t base = ((size_t)bh*NCH + c)*ED*ED + (size_t)t*16;
        #pragma unroll
        for (int i=0;i<16;i+=4)
            *(float4*)&g_Sin[base+i] = make_float4(s[i],s[i+1],s[i+2],s[i+3]);
        if (t < ED) g_zin[((size_t)bh*NCH+c)*ED + t] = z;
        #pragma unroll
        for (int i=0;i<16;i+=4){
            float4 lv = *(const float4*)&g_Sloc[base+i];
            s[i]   = lamC*s[i]   + lv.x;
            s[i+1] = lamC*s[i+1] + lv.y;
            s[i+2] = lamC*s[i+2] + lv.z;
            s[i+3] = lamC*s[i+3] + lv.w;
        }
        if (t < ED) z = lamC*z + g_zloc[((size_t)bh*NCH+c)*ED + t];
    }
}

// ---------------- per-chunk output --------------------------------------
// out_i = [ lam^{i+1} (Q S_in)_i + sum_{j<=i} lam^{i-j}(q_i.k_j) v_j ]
//       / [ lam^{i+1} (q_i.z_in) + sum_{j<=i} lam^{i-j}(q_i.k_j) + 1e-6 ]
__global__ __launch_bounds__(256) void chunk_out_kernel(const float* __restrict__ dl)
{
    extern __shared__ float sh[];
    float* Qs  = sh;              // 128 x 65
    float* Kt  = Qs  + 128*65;    // 64  x 132 (transposed K)
    float* Vs  = Kt  + 64*132;    // 128 x 68
    float* Ss  = Vs  + 128*68;    // 64  x 68
    float* Ps  = Ss  + 64*68;     // 128 x 132 (weighted scores)
    float* zs  = Ps  + 128*132;   // 64
    float* pw  = zs  + 64;        // 132 (lam^0..lam^128)
    float* dqs = pw  + 132;       // 128
    float* dens= dqs + 128;       // 128

    const int c = blockIdx.x, bh = blockIdx.y;
    const int b = bh / NH, h = bh % NH;
    const int t = threadIdx.x;
    const int tx = t & 15, ty = t >> 4;
    const float lam = lam_of(dl, h);
    if (t <= CK) pw[t] = exp2f((float)t * log2f(lam));

    const size_t rowbase = ((size_t)b*SL + (size_t)c*CK)*DM + h*ED;
    for (int vi = t; vi < CK*ED/4; vi += 256){
        const int r = vi >> 4, k4 = (vi & 15)*4;
        float4 qv = *(const float4*)&g_q[rowbase + (size_t)r*DM + k4];
        Qs[r*65 + k4+0]=qv.x; Qs[r*65 + k4+1]=qv.y;
        Qs[r*65 + k4+2]=qv.z; Qs[r*65 + k4+3]=qv.w;
        float4 kv = *(const float4*)&g_k[rowbase + (size_t)r*DM + k4];
        Kt[(k4+0)*132 + r]=kv.x; Kt[(k4+1)*132 + r]=kv.y;
        Kt[(k4+2)*132 + r]=kv.z; Kt[(k4+3)*132 + r]=kv.w;
        *(float4*)&Vs[r*68 + k4] = *(const float4*)&g_v[rowbase + (size_t)r*DM + k4];
    }
    const size_t sbase = ((size_t)bh*NCH + c)*ED*ED;
    for (int vi = t; vi < ED*ED/4; vi += 256){
        const int r = vi >> 4, f4 = (vi & 15)*4;
        *(float4*)&Ss[r*68 + f4] = *(const float4*)&g_Sin[sbase + r*ED + f4];
    }
    if (t < ED) zs[t] = g_zin[((size_t)bh*NCH+c)*ED + t];
    __syncthreads();

    // Phase 1: P = (Q K^T) with causal lam^{i-j} weighting
    {
        float accP[8][8];
        #pragma unroll
        for (int i=0;i<8;i++)
            #pragma unroll
            for (int j=0;j<8;j++) accP[i][j]=0.f;
        for (int k=0;k<ED;k++){
            float a[8];
            #pragma unroll
            for (int i=0;i<8;i++)
                a[i] = Qs[(ty*4 + (i&3) + (i>>2)*64)*65 + k];
            float4 b0 = *(const float4*)&Kt[k*132 + tx*4];
            float4 b1 = *(const float4*)&Kt[k*132 + tx*4 + 64];
            float bb[8] = {b0.x,b0.y,b0.z,b0.w,b1.x,b1.y,b1.z,b1.w};
            #pragma unroll
            for (int i=0;i<8;i++)
                #pragma unroll
                for (int j=0;j<8;j++) accP[i][j] = fmaf(a[i], bb[j], accP[i][j]);
        }
        #pragma unroll
        for (int i=0;i<8;i++){
            const int ii = ty*4 + (i&3) + (i>>2)*64;
            #pragma unroll
            for (int j=0;j<8;j++){
                const int jj = tx*4 + (j&3) + (j>>2)*64;
                const float w = (jj <= ii) ? pw[ii-jj] : 0.f;
                Ps[ii*132 + jj] = w * accP[i][j];
            }
        }
    }
    __syncthreads();

    // Phase 2: row sums (denominator pieces), threads 0..127
    if (t < CK){
        float d = 0.f;
        for (int j=0;j<CK;j++) d += Ps[t*132 + j];
        dens[t] = d;
        float q = 0.f;
        for (int k=0;k<ED;k++) q += Qs[t*65 + k] * zs[k];
        dqs[t] = q;
    }

    // Phase 3: acc1 = Q @ S_in ; acc2 = P @ V
    float acc1[8][4], acc2[8][4];
    #pragma unroll
    for (int i=0;i<8;i++)
        #pragma unroll
        for (int j=0;j<4;j++){ acc1[i][j]=0.f; acc2[i][j]=0.f; }
    for (int k=0;k<ED;k++){
        float4 sv = *(const float4*)&Ss[k*68 + tx*4];
        #pragma unroll
        for (int i=0;i<8;i++){
            const float qv = Qs[(ty*4 + (i&3) + (i>>2)*64)*65 + k];
            acc1[i][0] = fmaf(qv, sv.x, acc1[i][0]);
            acc1[i][1] = fmaf(qv, sv.y, acc1[i][1]);
            acc1[i][2] = fmaf(qv, sv.z, acc1[i][2]);
            acc1[i][3] = fmaf(qv, sv.w, acc1[i][3]);
        }
    }
    for (int k2=0;k2<CK;k2++){
        float4 vv = *(const float4*)&Vs[k2*68 + tx*4];
        #pragma unroll
        for (int i=0;i<8;i++){
            const float p = Ps[(ty*4 + (i&3) + (i>>2)*64)*132 + k2];
            acc2[i][0] = fmaf(p, vv.x, acc2[i][0]);
            acc2[i][1] = fmaf(p, vv.y, acc2[i][1]);
            acc2[i][2] = fmaf(p, vv.z, acc2[i][2]);
            acc2[i][3] = fmaf(p, vv.w, acc2[i][3]);
        }
    }
    __syncthreads();

    #pragma unroll
    for (int i=0;i<8;i++){
        const int ii = ty*4 + (i&3) + (i>>2)*64;
        const float pwi = pw[ii+1];
        const float dd  = pwi*dqs[ii] + dens[ii] + 1e-6f;
        const float inv = 1.f/dd;
        const int m = b*SL + c*CK + ii;
        #pragma unroll
        for (int j=0;j<4;j++){
            const float num = pwi*acc1[i][j] + acc2[i][j];
            g_attn[(size_t)m*DM + h*ED + tx*4 + j] = num*inv;
        }
    }
}

// ---------------- LayerNorm ------------------------------------------------
__global__ __launch_bounds__(128) void ln_kernel(const float* __restrict__ gg,
                                                 const float* __restrict__ bb,
                                                 float* __restrict__ out)
{
    const int row = blockIdx.x, t = threadIdx.x;
    __shared__ float red[8];
    float4 v = *(const float4*)&g_y[(size_t)row*DM + t*4];
    float s  = v.x+v.y+v.z+v.w;
    float s2 = v.x*v.x+v.y*v.y+v.z*v.z+v.w*v.w;
    #pragma unroll
    for (int o=16;o;o>>=1){
        s  += __shfl_xor_sync(0xffffffffu, s,  o);
        s2 += __shfl_xor_sync(0xffffffffu, s2, o);
    }
    const int w = t>>5;
    if ((t&31)==0){ red[w]=s; red[4+w]=s2; }
    __syncthreads();
    s  = red[0]+red[1]+red[2]+red[3];
    s2 = red[4]+red[5]+red[6]+red[7];
    const float mean = s*(1.0f/DM);
    const float var  = s2*(1.0f/DM) - mean*mean;
    const float inv  = rsqrtf(var + 1e-5f);
    float4 gv = *(const float4*)&gg[t*4];
    float4 bv = *(const float4*)&bb[t*4];
    float4 o;
    o.x = (v.x-mean)*inv*gv.x + bv.x;
    o.y = (v.y-mean)*inv*gv.y + bv.y;
    o.z = (v.z-mean)*inv*gv.z + bv.z;
    o.w = (v.w-mean)*inv*gv.w + bv.w;
    *(float4*)&out[(size_t)row*DM + t*4] = o;
}

// ---------------- launch ----------------------------------------------------
extern "C" void kernel_launch(void* const* d_in, const int* in_sizes, int n_in,
                              void* d_out, int out_size)
{
    const float* x     = (const float*)d_in[0];
    const float* W_qkv = (const float*)d_in[1];
    const float* b_qkv = (const float*)d_in[2];
    const float* W_out = (const float*)d_in[3];
    const float* b_out = (const float*)d_in[4];
    const float* dl    = (const float*)d_in[5];
    const float* ln_g  = (const float*)d_in[6];
    const float* ln_b  = (const float*)d_in[7];
    float* out = (float*)d_out;

    const int smem_cl = (CK*ED*2 + CK) * 4;                       // 66048 B
    const int smem_co = (128*65 + 64*132 + 128*68 + 64*68 +
                         128*132 + 64 + 132 + 128 + 128) * 4;     // 188688 B
    const int smem_mm = 2*8192*4;                                 // 65536 B
    cudaFuncSetAttribute(chunk_local_kernel,
                         cudaFuncAttributeMaxDynamicSharedMemorySize, smem_cl);
    cudaFuncSetAttribute(chunk_out_kernel,
                         cudaFuncAttributeMaxDynamicSharedMemorySize, smem_co);
    cudaFuncSetAttribute(mma_gemm_kernel<0>,
                         cudaFuncAttributeMaxDynamicSharedMemorySize, smem_mm);
    cudaFuncSetAttribute(mma_gemm_kernel<1>,
                         cudaFuncAttributeMaxDynamicSharedMemorySize, smem_mm);

    float* WqkvT; cudaGetSymbolAddress((void**)&WqkvT, g_WqkvT);
    float* WoutT; cudaGetSymbolAddress((void**)&WoutT, g_WoutT);

    transpose_kernel<<<dim3(48,16), dim3(32,8)>>>(W_qkv, WqkvT, DM, 3*DM);
    transpose_kernel<<<dim3(16,16), dim3(32,8)>>>(W_out, WoutT, DM, DM);
    mma_gemm_kernel<0><<<dim3(12,32), 256, smem_mm>>>(x, b_qkv);
    chunk_local_kernel<<<dim3(NCH,NBH),256,smem_cl>>>(dl);
    scan_kernel<<<NBH,256>>>(dl);
    chunk_out_kernel<<<dim3(NCH,NBH),256,smem_co>>>(dl);
    mma_gemm_kernel<1><<<dim3(4,32), 256, smem_mm>>>(nullptr, b_out);
    ln_kernel<<<MT,128>>>(ln_g, ln_b, out);
}

// round 6
// speedup vs baseline: 1.9297x; 1.1863x over previous
#include <cuda_runtime.h>
#include <math.h>
#include <stdint.h>

#define DM 512
#define NH 8
#define ED 64
#define NB 2
#define SL 2048
#define MT (NB*SL)          // 4096 rows
#define NBH (NB*NH)         // 16 sequences
#define CK 128              // chunk length
#define NCH (SL/CK)         // 16 chunks

// ---------------- scratch (static device globals; no runtime alloc) --------
__device__ float g_q[MT*DM];
__device__ float g_k[MT*DM];
__device__ float g_v[MT*DM];
__device__ float g_attn[MT*DM];
__device__ float g_y[MT*DM];
__device__ float g_WqkvT[3*DM*DM];   // [1536][512]
__device__ float g_WoutT[DM*DM];     // [512][512]
__device__ float g_Sloc[NBH*NCH*ED*ED];
__device__ float g_SinT[NBH*NCH*ED*ED];   // TRANSPOSED carry-in states [f][e]
__device__ float g_zloc[NBH*NCH*ED];
__device__ float g_zin [NBH*NCH*ED];

__device__ __forceinline__ float lam_of(const float* dl, int h){
    return 0.99f + 0.01f/(1.0f + expf(-dl[h]));
}
__device__ __forceinline__ uint32_t f2tf32(float x){
    uint32_t r; asm("cvt.rna.tf32.f32 %0, %1;" : "=r"(r) : "f"(x)); return r;
}
__device__ __forceinline__ void mma_tf32(float* c, const uint4& a, const uint2& b){
    asm volatile("mma.sync.aligned.m16n8k8.row.col.f32.tf32.tf32.f32 "
        "{%0,%1,%2,%3}, {%4,%5,%6,%7}, {%8,%9}, {%0,%1,%2,%3};"
        : "+f"(c[0]), "+f"(c[1]), "+f"(c[2]), "+f"(c[3])
        : "r"(a.x), "r"(a.y), "r"(a.z), "r"(a.w), "r"(b.x), "r"(b.y));
}
// fragment-pack index helpers (m16n8k8 tf32)
// A element (row r, k): lane=(r&7)*4+(k&3), reg=((r>>3)&1)+2*((k>>2)&1)
__device__ __forceinline__ int Aidx(int KS, int r, int k){
    return (((r>>4)*KS + (k>>3))*32 + (r&7)*4 + (k&3))*4 + ((r>>3)&1) + 2*((k>>2)&1);
}
// B element (n, k): lane=(n&7)*4+(k&3), reg=(k>>2)&1
__device__ __forceinline__ int Bidx(int KS, int n, int k){
    return (((n>>3)*KS + (k>>3))*32 + (n&7)*4 + (k&3))*2 + ((k>>2)&1);
}

// ---------------- W transpose: Wt[n][k] = W[k][n] ---------------------------
__global__ void transpose_kernel(const float* __restrict__ W, float* __restrict__ Wt,
                                 int K, int N)
{
    __shared__ float tile[32][33];
    const int n0 = blockIdx.x*32, k0 = blockIdx.y*32;
    const int tx = threadIdx.x, ty = threadIdx.y;   // 32 x 8
    #pragma unroll
    for (int j=0;j<32;j+=8)
        tile[ty+j][tx] = W[(size_t)(k0+ty+j)*N + n0+tx];
    __syncthreads();
    #pragma unroll
    for (int j=0;j<32;j+=8)
        Wt[(size_t)(n0+ty+j)*K + k0+tx] = tile[tx][ty+j];
}

// =================== tf32 mma.sync GEMM: D = A @ Wt^T + b ===================
template<int MODE>
__global__ __launch_bounds__(256) void mma_gemm_kernel(const float* __restrict__ Ain,
                                                       const float* __restrict__ bias)
{
    extern __shared__ uint32_t sm[];        // 2 bufs x (A 4096 + B 4096) u32
    const float* A  = (MODE==0) ? Ain : g_attn;
    const float* Wt = (MODE==0) ? g_WqkvT : g_WoutT;
    const int m0 = blockIdx.y*128, n0 = blockIdx.x*128;
    const int t = threadIdx.x, lane = t&31, wid = t>>5;
    const int wm = wid&1, wn = wid>>1;

    const int c4    = (t&7)<<2;
    const int kkL   = c4>>3;
    const int cregL = (c4>>2)&1;
    const int rlo   = t>>3;
    const int lane0 = (rlo&7)<<2;
    const int rhi   = (t>>6)&1;
    const int mt0   = t>>7;
    const int nt0   = (t>>6)&3;
    const int regA  = rhi + 2*cregL;

    float4 ra[4], rb[4];
    float acc[4][4][4];
    #pragma unroll
    for (int i=0;i<4;i++)
        #pragma unroll
        for (int j=0;j<4;j++)
            #pragma unroll
            for (int r=0;r<4;r++) acc[i][j][r]=0.f;

    auto ldg = [&](int c){
        const int k0 = c*32;
        #pragma unroll
        for (int i=0;i<4;i++){
            ra[i] = *(const float4*)&A [(size_t)(m0 + rlo + 32*i)*DM + k0 + c4];
            rb[i] = *(const float4*)&Wt[(size_t)(n0 + rlo + 32*i)*DM + k0 + c4];
        }
    };
    auto sts = [&](int buf){
        uint32_t* Ab = sm + buf*8192;
        uint32_t* Bb = Ab + 4096;
        #pragma unroll
        for (int i=0;i<4;i++){
            const int mt = mt0 + 2*i;
            const uint32_t ab = (uint32_t)(((mt*4 + kkL)*32 + lane0)*4 + regA);
            Ab[ab + 0*4] = f2tf32(ra[i].x);
            Ab[ab + 1*4] = f2tf32(ra[i].y);
            Ab[ab + 2*4] = f2tf32(ra[i].z);
            Ab[ab + 3*4] = f2tf32(ra[i].w);
            const int nt = nt0 + 4*i;
            const uint32_t bb = (uint32_t)(((nt*4 + kkL)*32 + lane0)*2 + cregL);
            Bb[bb + 0*2] = f2tf32(rb[i].x);
            Bb[bb + 1*2] = f2tf32(rb[i].y);
            Bb[bb + 2*2] = f2tf32(rb[i].z);
            Bb[bb + 3*2] = f2tf32(rb[i].w);
        }
    };
    auto compute = [&](int buf){
        const uint32_t* Ab = sm + buf*8192;
        const uint32_t* Bb = Ab + 4096;
        #pragma unroll
        for (int kk=0;kk<4;kk++){
            uint4 a[4]; uint2 b[4];
            #pragma unroll
            for (int i=0;i<4;i++)
                a[i] = *(const uint4*)&Ab[(((wm*4+i)*4+kk)*32 + lane)*4];
            #pragma unroll
            for (int j=0;j<4;j++)
                b[j] = *(const uint2*)&Bb[(((wn*4+j)*4+kk)*32 + lane)*2];
            #pragma unroll
            for (int i=0;i<4;i++)
                #pragma unroll
                for (int j=0;j<4;j++)
                    mma_tf32(acc[i][j], a[i], b[j]);
        }
    };

    ldg(0); sts(0); __syncthreads();
    #pragma unroll 1
    for (int c=0;c<16;c++){
        if (c<15) ldg(c+1);
        compute(c&1);
        if (c<15) sts((c+1)&1);
        __syncthreads();
    }

    int regi = 0; float* dst;
    if (MODE==0){
        regi = n0 >> 9;
        dst = (regi==0) ? g_q : (regi==1) ? g_k : g_v;
    } else dst = g_y;
    const int nsub = (MODE==0) ? (n0 - regi*512) : n0;
    const int rowl = lane>>2, colp = (lane&3)*2;

    #pragma unroll
    for (int i=0;i<4;i++){
        #pragma unroll
        for (int j=0;j<4;j++){
            const int nn = n0   + wn*32 + j*8 + colp;
            const int nc = nsub + wn*32 + j*8 + colp;
            const float b0v = __ldg(&bias[nn]);
            const float b1v = __ldg(&bias[nn+1]);
            float v[4] = { acc[i][j][0] + b0v, acc[i][j][1] + b1v,
                           acc[i][j][2] + b0v, acc[i][j][3] + b1v };
            if (MODE==0 && regi==0){
                #pragma unroll
                for (int e=0;e<4;e++){ float x=(v[e]>0.f)?v[e]+1.f:expf(v[e]); v[e]=x*0.125f; }
            } else if (MODE==0 && regi==1){
                #pragma unroll
                for (int e=0;e<4;e++){ float x=(v[e]>0.f)?v[e]+1.f:expf(v[e]); v[e]=x; }
            }
            const int r0 = m0 + wm*64 + i*16 + rowl;
            *(float2*)&dst[(size_t)r0*DM + nc]     = make_float2(v[0], v[1]);
            *(float2*)&dst[(size_t)(r0+8)*DM + nc] = make_float2(v[2], v[3]);
        }
    }
}

// ============== chunk_local via mma: S_loc = (pw*K)^T @ V,  64x64x128 =======
__global__ __launch_bounds__(256) void chunk_local_kernel(const float* __restrict__ dl)
{
    extern __shared__ float sh[];
    float*    Kc = sh;                          // 128x64
    float*    Vc = Kc + 8192;                   // 128x64
    uint32_t* Aa = (uint32_t*)(Vc + 8192);      // A-pack 64x128 (KS=16)
    uint32_t* Bb = Aa + 8192;                   // B-pack 64x128 (KS=16)
    __shared__ float pw[128];

    const int c = blockIdx.x, bh = blockIdx.y;
    const int b = bh / NH, h = bh % NH;
    const int t = threadIdx.x, lane = t&31, wid = t>>5;
    const int wm = wid&1, wn = wid>>1;
    const int g = lane>>2, tg = lane&3;
    const float lam = lam_of(dl, h);
    if (t < 128) pw[t] = exp2f((float)t * log2f(lam));

    const size_t rowbase = ((size_t)b*SL + (size_t)c*CK)*DM + h*ED;
    for (int vi = t; vi < CK*ED/4; vi += 256){
        const int j = vi >> 4, e4 = (vi & 15)*4;
        *(float4*)&Kc[j*ED + e4] = *(const float4*)&g_k[rowbase + (size_t)j*DM + e4];
        *(float4*)&Vc[j*ED + e4] = *(const float4*)&g_v[rowbase + (size_t)j*DM + e4];
    }
    __syncthreads();

    // pack A[e][j] = pw[127-j]*K[j][e]; B[f][j] = V[j][f]
    for (int idx = t; idx < 8192; idx += 256){
        const int j = idx >> 6, e = idx & 63;
        Aa[Aidx(16, e, j)] = f2tf32(pw[127-j] * Kc[idx]);
        Bb[Bidx(16, e, j)] = f2tf32(Vc[idx]);
    }
    // z_loc (deterministic)
    if (t < ED){
        float z = 0.f;
        for (int j=0;j<CK;j++) z += pw[127-j]*Kc[j*ED + t];
        g_zloc[((size_t)bh*NCH + c)*ED + t] = z;
    }
    __syncthreads();

    float acc[2][2][4];
    #pragma unroll
    for (int i=0;i<2;i++)
        #pragma unroll
        for (int j=0;j<2;j++)
            #pragma unroll
            for (int r=0;r<4;r++) acc[i][j][r]=0.f;
    #pragma unroll
    for (int kk=0;kk<16;kk++){
        uint4 a[2]; uint2 b2[2];
        #pragma unroll
        for (int i=0;i<2;i++)
            a[i] = *(const uint4*)&Aa[(((wm*2+i)*16+kk)*32 + lane)*4];
        #pragma unroll
        for (int j=0;j<2;j++)
            b2[j] = *(const uint2*)&Bb[(((wn*2+j)*16+kk)*32 + lane)*2];
        #pragma unroll
        for (int i=0;i<2;i++)
            #pragma unroll
            for (int j=0;j<2;j++)
                mma_tf32(acc[i][j], a[i], b2[j]);
    }
    const size_t sb = ((size_t)bh*NCH + c)*ED*ED;
    #pragma unroll
    for (int i=0;i<2;i++){
        #pragma unroll
        for (int j=0;j<2;j++){
            const int e0 = wm*32 + i*16 + g;
            const int f0 = wn*16 + j*8 + tg*2;
            *(float2*)&g_Sloc[sb + e0*ED + f0]     = make_float2(acc[i][j][0], acc[i][j][1]);
            *(float2*)&g_Sloc[sb + (e0+8)*ED + f0] = make_float2(acc[i][j][2], acc[i][j][3]);
        }
    }
}

// ---------------- inter-chunk prefix scan (stores S_in TRANSPOSED) ---------
__global__ __launch_bounds__(256) void scan_kernel(const float* __restrict__ dl)
{
    const int bh = blockIdx.x;
    const int h = bh % NH;
    const int t = threadIdx.x;
    const float lam  = lam_of(dl, h);
    const float lamC = exp2f((float)CK * log2f(lam));
    float s[16];
    #pragma unroll
    for (int i=0;i<16;i++) s[i]=0.f;
    float z = 0.f;
    const int e  = t >> 2;           // row of S
    const int f0 = (t & 3)*16;       // col base
    for (int c = 0; c < NCH; c++){
        const size_t base = ((size_t)bh*NCH + c)*ED*ED;
        #pragma unroll
        for (int i=0;i<16;i++)
            g_SinT[base + (size_t)(f0+i)*ED + e] = s[i];   // transposed store
        if (t < ED) g_zin[((size_t)bh*NCH+c)*ED + t] = z;
        #pragma unroll
        for (int i=0;i<16;i+=4){
            float4 lv = *(const float4*)&g_Sloc[base + (size_t)t*16 + i];
            s[i]   = lamC*s[i]   + lv.x;
            s[i+1] = lamC*s[i+1] + lv.y;
            s[i+2] = lamC*s[i+2] + lv.z;
            s[i+3] = lamC*s[i+3] + lv.w;
        }
        if (t < ED) z = lamC*z + g_zloc[((size_t)bh*NCH+c)*ED + t];
    }
}

// ================= chunk_out via mma =======================================
// P = QK^T (masked/weighted), acc1 = Q@S_in, acc2 = P@V,
// out = (pw[i+1]*acc1 + acc2) / (pw[i+1]*(q.z_in) + rowsum(P) + 1e-6)
__global__ __launch_bounds__(256) void chunk_out_kernel(const float* __restrict__ dl)
{
    extern __shared__ uint32_t su[];
    uint32_t* Qa = su;             // A-pack Q  128x64  (KS=8)  : 8192
    uint32_t* Kb = Qa + 8192;      // B-pack K  n=128,k=64      : 8192
    uint32_t* Pa = Kb + 8192;      // A-pack P  128x128 (KS=16) : 16384
    uint32_t* Vb = Pa + 16384;     // B-pack V^T n=64,k=128     : 8192
    uint32_t* Sb = Vb + 8192;      // B-pack S^T n=64,k=64      : 4096
    float*    Vs = (float*)(Sb + 4096);  // plain V staging 128x64 : 8192
    __shared__ float pw[132];
    __shared__ float dens2[4][128];
    __shared__ float dens[128];
    __shared__ float dqs[128];
    __shared__ float zs[64];

    const int c = blockIdx.x, bh = blockIdx.y;
    const int b = bh / NH, h = bh % NH;
    const int t = threadIdx.x, lane = t&31, wid = t>>5;
    const int wm = wid&1, wn = wid>>1;
    const int g = lane>>2, tg = lane&3;
    const float lam = lam_of(dl, h);
    if (t <= 128) pw[t] = exp2f((float)t * log2f(lam));
    if (t < ED)   zs[t] = g_zin[((size_t)bh*NCH+c)*ED + t];

    const size_t rowbase = ((size_t)b*SL + (size_t)c*CK)*DM + h*ED;
    // stage A: packs of Q, K; plain V staging
    for (int idx = t; idx < 8192; idx += 256){
        const int r = idx >> 6, k = idx & 63;
        Qa[Aidx(8, r, k)] = f2tf32(g_q[rowbase + (size_t)r*DM + k]);
        Kb[Bidx(8, r, k)] = f2tf32(g_k[rowbase + (size_t)r*DM + k]);
    }
    for (int vi = t; vi < 2048; vi += 256){
        const int j = vi >> 4, e4 = (vi & 15)*4;
        *(float4*)&Vs[j*ED + e4] = *(const float4*)&g_v[rowbase + (size_t)j*DM + e4];
    }
    __syncthreads();

    // phase 1: P = Q K^T  (warp tile 64x32 over (i,jj))
    float accP[4][4][4];
    #pragma unroll
    for (int i=0;i<4;i++)
        #pragma unroll
        for (int j=0;j<4;j++)
            #pragma unroll
            for (int r=0;r<4;r++) accP[i][j][r]=0.f;
    #pragma unroll
    for (int kk=0;kk<8;kk++){
        uint4 a[4]; uint2 b2[4];
        #pragma unroll
        for (int i=0;i<4;i++)
            a[i] = *(const uint4*)&Qa[(((wm*4+i)*8+kk)*32 + lane)*4];
        #pragma unroll
        for (int j=0;j<4;j++)
            b2[j] = *(const uint2*)&Kb[(((wn*4+j)*8+kk)*32 + lane)*2];
        #pragma unroll
        for (int i=0;i<4;i++)
            #pragma unroll
            for (int j=0;j<4;j++)
                mma_tf32(accP[i][j], a[i], b2[j]);
    }

    // stage B: weight+mask, repack P into A-frag layout; dens partials; dqs;
    //          pack V^T and S^T operands
    #pragma unroll
    for (int i=0;i<4;i++){
        float rs_lo = 0.f, rs_hi = 0.f;
        const int ii_lo = wm*64 + i*16 + g;
        const int ii_hi = ii_lo + 8;
        #pragma unroll
        for (int j=0;j<4;j++){
            #pragma unroll
            for (int r=0;r<4;r++){
                const int ii = (r<2) ? ii_lo : ii_hi;
                const int jj = wn*32 + j*8 + tg*2 + (r&1);
                const float w = (jj <= ii) ? pw[ii-jj] : 0.f;
                const float val = w * accP[i][j][r];
                Pa[Aidx(16, ii, jj)] = f2tf32(val);
                if (r<2) rs_lo += val; else rs_hi += val;
            }
        }
        rs_lo += __shfl_down_sync(0xffffffffu, rs_lo, 2, 4);
        rs_lo += __shfl_down_sync(0xffffffffu, rs_lo, 1, 4);
        rs_hi += __shfl_down_sync(0xffffffffu, rs_hi, 2, 4);
        rs_hi += __shfl_down_sync(0xffffffffu, rs_hi, 1, 4);
        if (tg == 0){
            dens2[wn][ii_lo] = rs_lo;
            dens2[wn][ii_hi] = rs_hi;
        }
    }
    // dqs: unpack Qa row t, dot with zs
    if (t < 128){
        float q = 0.f;
        #pragma unroll 4
        for (int e=0;e<ED;e++)
            q += __uint_as_float(Qa[Aidx(8, t, e)]) * zs[e];
        dqs[t] = q;
    }
    // pack V^T: B[n=f][k=j] = Vs[j][f]
    for (int idx = t; idx < 8192; idx += 256){
        const int j = idx >> 6, f = idx & 63;
        Vb[Bidx(16, f, j)] = f2tf32(Vs[idx]);
    }
    // pack S^T: B[n=f][k=e] = SinT[f][e] (coalesced from transposed scan output)
    {
        const size_t sbase = ((size_t)bh*NCH + c)*ED*ED;
        for (int idx = t; idx < 4096; idx += 256){
            const int f = idx >> 6, e = idx & 63;
            Sb[Bidx(8, f, e)] = f2tf32(g_SinT[sbase + idx]);
        }
    }
    __syncthreads();

    // dens combine (deterministic)
    if (t < 128)
        dens[t] = dens2[0][t] + dens2[1][t] + dens2[2][t] + dens2[3][t];

    // phase 3: acc1 = Q @ S_in (K=64), acc2 = P @ V (K=128); warp tile 64x16
    float acc1[4][2][4], acc2[4][2][4];
    #pragma unroll
    for (int i=0;i<4;i++)
        #pragma unroll
        for (int j=0;j<2;j++)
            #pragma unroll
            for (int r=0;r<4;r++){ acc1[i][j][r]=0.f; acc2[i][j][r]=0.f; }
    #pragma unroll
    for (int kk=0;kk<8;kk++){
        uint4 a[4]; uint2 b2[2];
        #pragma unroll
        for (int i=0;i<4;i++)
            a[i] = *(const uint4*)&Qa[(((wm*4+i)*8+kk)*32 + lane)*4];
        #pragma unroll
        for (int j=0;j<2;j++)
            b2[j] = *(const uint2*)&Sb[(((wn*2+j)*8+kk)*32 + lane)*2];
        #pragma unroll
        for (int i=0;i<4;i++)
            #pragma unroll
            for (int j=0;j<2;j++)
                mma_tf32(acc1[i][j], a[i], b2[j]);
    }
    #pragma unroll
    for (int kk=0;kk<16;kk++){
        uint4 a[4]; uint2 b2[2];
        #pragma unroll
        for (int i=0;i<4;i++)
            a[i] = *(const uint4*)&Pa[(((wm*4+i)*16+kk)*32 + lane)*4];
        #pragma unroll
        for (int j=0;j<2;j++)
            b2[j] = *(const uint2*)&Vb[(((wn*2+j)*16+kk)*32 + lane)*2];
        #pragma unroll
        for (int i=0;i<4;i++)
            #pragma unroll
            for (int j=0;j<2;j++)
                mma_tf32(acc2[i][j], a[i], b2[j]);
    }
    __syncthreads();   // dens ready for all

    // final: combine, divide, store
    const int mrow = b*SL + c*CK;
    #pragma unroll
    for (int i=0;i<4;i++){
        const int ii_lo = wm*64 + i*16 + g;
        #pragma unroll
        for (int rr=0;rr<2;rr++){
            const int ii = ii_lo + rr*8;
            const float pwi = pw[ii+1];
            const float inv = 1.f / (pwi*dqs[ii] + dens[ii] + 1e-6f);
            #pragma unroll
            for (int j=0;j<2;j++){
                const int f0 = wn*16 + j*8 + tg*2;
                const float v0 = (pwi*acc1[i][j][rr*2+0] + acc2[i][j][rr*2+0])*inv;
                const float v1 = (pwi*acc1[i][j][rr*2+1] + acc2[i][j][rr*2+1])*inv;
                *(float2*)&g_attn[(size_t)(mrow+ii)*DM + h*ED + f0] = make_float2(v0, v1);
            }
        }
    }
}

// ---------------- LayerNorm ------------------------------------------------
__global__ __launch_bounds__(128) void ln_kernel(const float* __restrict__ gg,
                                                 const float* __restrict__ bb,
                                                 float* __restrict__ out)
{
    const int row = blockIdx.x, t = threadIdx.x;
    __shared__ float red[8];
    float4 v = *(const float4*)&g_y[(size_t)row*DM + t*4];
    float s  = v.x+v.y+v.z+v.w;
    float s2 = v.x*v.x+v.y*v.y+v.z*v.z+v.w*v.w;
    #pragma unroll
    for (int o=16;o;o>>=1){
        s  += __shfl_xor_sync(0xffffffffu, s,  o);
        s2 += __shfl_xor_sync(0xffffffffu, s2, o);
    }
    const int w = t>>5;
    if ((t&31)==0){ red[w]=s; red[4+w]=s2; }
    __syncthreads();
    s  = red[0]+red[1]+red[2]+red[3];
    s2 = red[4]+red[5]+red[6]+red[7];
    const float mean = s*(1.0f/DM);
    const float var  = s2*(1.0f/DM) - mean*mean;
    const float inv  = rsqrtf(var + 1e-5f);
    float4 gv = *(const float4*)&gg[t*4];
    float4 bv = *(const float4*)&bb[t*4];
    float4 o;
    o.x = (v.x-mean)*inv*gv.x + bv.x;
    o.y = (v.y-mean)*inv*gv.y + bv.y;
    o.z = (v.z-mean)*inv*gv.z + bv.z;
    o.w = (v.w-mean)*inv*gv.w + bv.w;
    *(float4*)&out[(size_t)row*DM + t*4] = o;
}

// ---------------- launch ----------------------------------------------------
extern "C" void kernel_launch(void* const* d_in, const int* in_sizes, int n_in,
                              void* d_out, int out_size)
{
    const float* x     = (const float*)d_in[0];
    const float* W_qkv = (const float*)d_in[1];
    const float* b_qkv = (const float*)d_in[2];
    const float* W_out = (const float*)d_in[3];
    const float* b_out = (const float*)d_in[4];
    const float* dl    = (const float*)d_in[5];
    const float* ln_g  = (const float*)d_in[6];
    const float* ln_b  = (const float*)d_in[7];
    float* out = (float*)d_out;

    const int smem_cl = (8192+8192)*4 + (8192+8192)*4;            // 131072 B
    const int smem_co = (8192+8192+16384+8192+4096+8192)*4;       // 212992 B
    const int smem_mm = 2*8192*4;                                 // 65536 B
    cudaFuncSetAttribute(chunk_local_kernel,
                         cudaFuncAttributeMaxDynamicSharedMemorySize, smem_cl);
    cudaFuncSetAttribute(chunk_out_kernel,
                         cudaFuncAttributeMaxDynamicSharedMemorySize, smem_co);
    cudaFuncSetAttribute(mma_gemm_kernel<0>,
                         cudaFuncAttributeMaxDynamicSharedMemorySize, smem_mm);
    cudaFuncSetAttribute(mma_gemm_kernel<1>,
                         cudaFuncAttributeMaxDynamicSharedMemorySize, smem_mm);

    float* WqkvT; cudaGetSymbolAddress((void**)&WqkvT, g_WqkvT);
    float* WoutT; cudaGetSymbolAddress((void**)&WoutT, g_WoutT);

    transpose_kernel<<<dim3(48,16), dim3(32,8)>>>(W_qkv, WqkvT, DM, 3*DM);
    transpose_kernel<<<dim3(16,16), dim3(32,8)>>>(W_out, WoutT, DM, DM);
    mma_gemm_kernel<0><<<dim3(12,32), 256, smem_mm>>>(x, b_qkv);
    chunk_local_kernel<<<dim3(NCH,NBH),256,smem_cl>>>(dl);
    scan_kernel<<<NBH,256>>>(dl);
    chunk_out_kernel<<<dim3(NCH,NBH),256,smem_co>>>(dl);
    mma_gemm_kernel<1><<<dim3(4,32), 256, smem_mm>>>(nullptr, b_out);
    ln_kernel<<<MT,128>>>(ln_g, ln_b, out);
}